// round 14
// baseline (speedup 1.0000x reference)
#include <cuda_runtime.h>
#include <cuda_bf16.h>
#include <cstdint>

// Differential attention via warp-level bf16 MMA (mma.sync m16n8k16, sm_80+ ISA).
// 512 threads / 16 warps (4 per SMSP), key-split QK + dim-split PV per warp pair,
// P exchanged through smem with a named barrier. Double-buffered K/V prefetch.
// Q (1,16,2048,128) fp32, K/V (1,4,2048,128) fp32, out fp32. Causal, GQA rep=4.
// Per half h: S_h = (Q_h K_h^T)/8; P_h = exp(S_h) (no max shift; |S| small),
// masked -> 0.  O_h = sum P_h V (fp32 accum in MMA C-frags).
// out = (O1/l1 - 0.8*O2/l2) * 0.2,  l = rowsum(P).
// Precision: x ~= xh + xl (bf16 each); X*Y ~= Xh*Yh + Xl*Yh + Xh*Yl.

#define S_LEN   2048
#define NHEADS  16
#define DIM     128
#define HALF    64
#define BQ      64
#define BK      32
#define NTHR    512
#define QTILES  (S_LEN / BQ)      // 32

#define SCALE_QK   0.125f
#define LAMBDA_V   0.8f
#define OUT_SCALE  0.19999999999999996f

// bf16 tiles, row stride 136 elements = 272 bytes (16B aligned, bank-spread)
#define RSTRB  272
// smem byte map
#define OFF_QH   0                  // 64 x 272 = 17408
#define OFF_QL   17408
#define OFF_B0   34816              // K/V buffer 0 (KH,KL,VH,VL x 8704)
#define BUFSTR   34816              // buffer stride (B1 = 69632)
#define KHOFF    0
#define KLOFF    8704
#define VHOFF    17408
#define VLOFF    26112
#define OFF_PX   104448             // P exchange: 16 warps x 32 lanes x 32B = 16384
#define OFF_RS   120832             // RS1[64] f32 then RS2[64] f32
#define SMEM_BYTES 121344
// epilogue O2 exchange buffer reuses Q region: f32 [64][132] = 33792 B
#define OFF_OB   0
#define OBSTR    132

__device__ __forceinline__ uint32_t smem_u32(const void* p) {
    uint32_t a;
    asm("{ .reg .u64 t; cvta.to.shared.u64 t, %1; cvt.u32.u64 %0, t; }"
        : "=r"(a) : "l"(p));
    return a;
}
__device__ __forceinline__ void ldsm4(uint32_t* r, uint32_t a) {
    asm volatile("ldmatrix.sync.aligned.m8n8.x4.shared.b16 {%0,%1,%2,%3}, [%4];"
        : "=r"(r[0]), "=r"(r[1]), "=r"(r[2]), "=r"(r[3]) : "r"(a));
}
__device__ __forceinline__ void ldsm4t(uint32_t* r, uint32_t a) {
    asm volatile("ldmatrix.sync.aligned.m8n8.x4.trans.shared.b16 {%0,%1,%2,%3}, [%4];"
        : "=r"(r[0]), "=r"(r[1]), "=r"(r[2]), "=r"(r[3]) : "r"(a));
}
__device__ __forceinline__ void mma16816(float* c, const uint32_t* a,
                                         uint32_t b0, uint32_t b1) {
    asm volatile("mma.sync.aligned.m16n8k16.row.col.f32.bf16.bf16.f32 "
        "{%0,%1,%2,%3}, {%4,%5,%6,%7}, {%8,%9}, {%0,%1,%2,%3};"
        : "+f"(c[0]), "+f"(c[1]), "+f"(c[2]), "+f"(c[3])
        : "r"(a[0]), "r"(a[1]), "r"(a[2]), "r"(a[3]), "r"(b0), "r"(b1));
}
// split two floats into packed bf16x2 hi and lo (x = hi + lo)
__device__ __forceinline__ void split2(float x0, float x1, uint32_t& h, uint32_t& l) {
    __nv_bfloat16 h0 = __float2bfloat16(x0), h1 = __float2bfloat16(x1);
    __nv_bfloat16 l0 = __float2bfloat16(x0 - __bfloat162float(h0));
    __nv_bfloat16 l1 = __float2bfloat16(x1 - __bfloat162float(h1));
    h = (uint32_t)__bfloat16_as_ushort(h0) | ((uint32_t)__bfloat16_as_ushort(h1) << 16);
    l = (uint32_t)__bfloat16_as_ushort(l0) | ((uint32_t)__bfloat16_as_ushort(l1) << 16);
}

__global__ __launch_bounds__(NTHR, 1)
void diffattn_mma4_kernel(const float* __restrict__ Qg_all,
                          const float* __restrict__ Kg_all,
                          const float* __restrict__ Vg_all,
                          float* __restrict__ Og_all)
{
    extern __shared__ char smc[];
    const uint32_t sb = smem_u32(smc);
    float* RS = (float*)(smc + OFF_RS);      // RS[0..63]=l1, RS[64..127]=l2
    float* OB = (float*)(smc + OFF_OB);      // epilogue only

    const int bid = blockIdx.x;
    const int h   = bid & 15;
    const int qt  = (QTILES - 1) - (bid >> 4);   // heavy q-tiles first
    const int kvh = h >> 2;
    const int t   = threadIdx.x;
    const int w   = t >> 5;
    const int lane = t & 31;
    const int g    = lane >> 2;     // 0..7
    const int tg   = lane & 3;      // 0..3
    const int l8   = lane & 7;
    const int mq   = lane >> 3;     // 0..3 (ldmatrix quad)
    const int half = w >> 3;        // 0: attn1, 1: attn2
    const int qb   = (w >> 1) & 3;  // 16-row stripe
    const int dh   = w & 1;         // key/dim split within pair
    const int pair = w >> 1;        // 0..7
    const int barid = 1 + pair;     // named barrier id
    const int d0h  = half * HALF;

    const float* Qg = Qg_all + ((size_t)h   * S_LEN + (size_t)qt * BQ) * DIM;
    const float* Kg = Kg_all + ((size_t)kvh * S_LEN) * DIM;
    const float* Vg = Vg_all + ((size_t)kvh * S_LEN) * DIM;
    float*       Og = Og_all + ((size_t)h   * S_LEN + (size_t)qt * BQ) * DIM;

    // ---- prologue: zero RS, Q -> smem bf16 hi/lo (scaled); prefetch tile 0 ----
    if (t < 128) RS[t] = 0.f;
    float4 kreg[2], vreg[2];
    {
        const float4* Kt4 = (const float4*)Kg;
        const float4* Vt4 = (const float4*)Vg;
        #pragma unroll
        for (int i = 0; i < 2; i++) {
            kreg[i] = Kt4[t + i * NTHR];
            vreg[i] = Vt4[t + i * NTHR];
        }
        const float4* Qg4 = (const float4*)Qg;
        #pragma unroll
        for (int i = 0; i < 4; i++) {
            int idx = t + i * NTHR;          // 0..2047
            int c = idx & 31, q = idx >> 5;
            float4 v = Qg4[idx];
            v.x *= SCALE_QK; v.y *= SCALE_QK; v.z *= SCALE_QK; v.w *= SCALE_QK;
            uint32_t h0, l0, h1, l1;
            split2(v.x, v.y, h0, l0);
            split2(v.z, v.w, h1, l1);
            *(uint2*)(smc + OFF_QH + q * RSTRB + c * 8) = make_uint2(h0, h1);
            *(uint2*)(smc + OFF_QL + q * RSTRB + c * 8) = make_uint2(l0, l1);
        }
    }
    // convert + store tile 0 into buffer 0
    {
        char* kv = smc + OFF_B0;
        #pragma unroll
        for (int i = 0; i < 2; i++) {
            int idx = t + i * NTHR;
            int c = idx & 31, k = idx >> 5;
            uint32_t h0, l0, h1, l1;
            split2(kreg[i].x, kreg[i].y, h0, l0);
            split2(kreg[i].z, kreg[i].w, h1, l1);
            *(uint2*)(kv + KHOFF + k * RSTRB + c * 8) = make_uint2(h0, h1);
            *(uint2*)(kv + KLOFF + k * RSTRB + c * 8) = make_uint2(l0, l1);
            split2(vreg[i].x, vreg[i].y, h0, l0);
            split2(vreg[i].z, vreg[i].w, h1, l1);
            *(uint2*)(kv + VHOFF + k * RSTRB + c * 8) = make_uint2(h0, h1);
            *(uint2*)(kv + VLOFF + k * RSTRB + c * 8) = make_uint2(l0, l1);
        }
    }
    __syncthreads();

    uint32_t qhf[4][4], qlf[4][4];   // Q A-frags per k-step (persistent)
    {
        const int row = 16 * qb + (mq & 1) * 8 + l8;
        #pragma unroll
        for (int s = 0; s < 4; s++) {
            const int col = d0h + 16 * s + (mq >> 1) * 8;
            ldsm4(qhf[s], sb + OFF_QH + row * RSTRB + col * 2);
            ldsm4(qlf[s], sb + OFF_QL + row * RSTRB + col * 2);
        }
    }

    // ---- persistent state ----
    float o[8][4];                   // O C-frags, dims 64*dh + 8*nb + {2tg,2tg+1}
    #pragma unroll
    for (int nb = 0; nb < 8; nb++)
        #pragma unroll
        for (int e = 0; e < 4; e++) o[nb][e] = 0.f;
    float rs_lo = 0.f, rs_hi = 0.f;  // partial row sums (this warp's 16 keys)

    const int qbase = qt * BQ;
    const int q_lo = qbase + 16 * qb + g;
    const int q_hi = q_lo + 8;
    const int nkt = 2 * qt + 2;
    // generic pointers into the P-exchange region (NOT shared-space ints)
    char* px_own = smc + OFF_PX + ((pair * 2 + dh) * 32 + lane) * 32;
    char* px_par = smc + OFF_PX + ((pair * 2 + (1 - dh)) * 32 + lane) * 32;

    for (int kt = 0; kt < nkt; kt++) {
        const int kbase = kt * BK;
        const uint32_t kvb = sb + OFF_B0 + (uint32_t)(kt & 1) * BUFSTR;
        const bool pf = (kt + 1 < nkt);

        // ---- prefetch next tile's globals into registers ----
        if (pf) {
            const float4* Kt4 = (const float4*)(Kg + (size_t)(kbase + BK) * DIM);
            const float4* Vt4 = (const float4*)(Vg + (size_t)(kbase + BK) * DIM);
            #pragma unroll
            for (int i = 0; i < 2; i++) {
                kreg[i] = Kt4[t + i * NTHR];
                vreg[i] = Vt4[t + i * NTHR];
            }
        }

        // ---- QK: S(16q x 16 keys [kbase+16*dh ..)), 3-term bf16 split ----
        float c4[2][4];
        #pragma unroll
        for (int nb = 0; nb < 2; nb++)
            #pragma unroll
            for (int e = 0; e < 4; e++) c4[nb][e] = 0.f;

        {
            const int krow = 16 * dh + 8 * (mq >> 1) + l8;
            #pragma unroll
            for (int s = 0; s < 4; s++) {
                const int col = d0h + 16 * s + (mq & 1) * 8;
                uint32_t kh[4], kl[4];
                ldsm4(kh, kvb + KHOFF + krow * RSTRB + col * 2);
                ldsm4(kl, kvb + KLOFF + krow * RSTRB + col * 2);
                mma16816(c4[0], qhf[s], kh[0], kh[1]);
                mma16816(c4[1], qhf[s], kh[2], kh[3]);
                mma16816(c4[0], qlf[s], kh[0], kh[1]);
                mma16816(c4[1], qlf[s], kh[2], kh[3]);
                mma16816(c4[0], qhf[s], kl[0], kl[1]);
                mma16816(c4[1], qhf[s], kl[2], kl[3]);
            }
        }

        // ---- exp + mask in registers; pack P as A-frags (hi/lo) ----
        uint32_t pah[4], pal[4];
        #pragma unroll
        for (int nb = 0; nb < 2; nb++) {
            const int k0 = kbase + 16 * dh + 8 * nb + 2 * tg;
            float p00 = (k0     <= q_lo) ? __expf(c4[nb][0]) : 0.f;
            float p01 = (k0 + 1 <= q_lo) ? __expf(c4[nb][1]) : 0.f;
            float p10 = (k0     <= q_hi) ? __expf(c4[nb][2]) : 0.f;
            float p11 = (k0 + 1 <= q_hi) ? __expf(c4[nb][3]) : 0.f;
            rs_lo += p00 + p01;
            rs_hi += p10 + p11;
            split2(p00, p01, pah[2 * nb + 0], pal[2 * nb + 0]);
            split2(p10, p11, pah[2 * nb + 1], pal[2 * nb + 1]);
        }

        // ---- exchange P frags within the dh-pair (named barrier) ----
        *(uint4*)(px_own +  0) = make_uint4(pah[0], pah[1], pah[2], pah[3]);
        *(uint4*)(px_own + 16) = make_uint4(pal[0], pal[1], pal[2], pal[3]);
        asm volatile("bar.sync %0, 64;" :: "r"(barid) : "memory");
        uint32_t pbh[4], pbl[4];
        {
            uint4 vh4 = *(uint4*)(px_par +  0);
            uint4 vl4 = *(uint4*)(px_par + 16);
            pbh[0] = vh4.x; pbh[1] = vh4.y; pbh[2] = vh4.z; pbh[3] = vh4.w;
            pbl[0] = vl4.x; pbl[1] = vl4.y; pbl[2] = vl4.z; pbl[3] = vl4.w;
        }

        // ---- PV: O(16q x 64 dims [64*dh..)) += Ph*Vh + Pl*Vh + Ph*Vl ----
        #pragma unroll
        for (int ks = 0; ks < 2; ks++) {
            const uint32_t* Ah = (ks == dh) ? pah : pbh;
            const uint32_t* Al = (ks == dh) ? pal : pbl;
            const int vrow = 16 * ks + (mq & 1) * 8 + l8;
            #pragma unroll
            for (int nbp = 0; nbp < 4; nbp++) {
                const int vcol = 64 * dh + 8 * (2 * nbp + (mq >> 1));
                uint32_t vh[4], vl[4];
                ldsm4t(vh, kvb + VHOFF + vrow * RSTRB + vcol * 2);
                ldsm4t(vl, kvb + VLOFF + vrow * RSTRB + vcol * 2);
                const int nb0 = 2 * nbp, nb1 = nb0 + 1;
                mma16816(o[nb0], Ah, vh[0], vh[1]);
                mma16816(o[nb1], Ah, vh[2], vh[3]);
                mma16816(o[nb0], Al, vh[0], vh[1]);
                mma16816(o[nb1], Al, vh[2], vh[3]);
                mma16816(o[nb0], Ah, vl[0], vl[1]);
                mma16816(o[nb1], Ah, vl[2], vl[3]);
            }
        }

        // ---- convert + store prefetched tile into the other buffer ----
        if (pf) {
            char* kv = smc + OFF_B0 + ((kt + 1) & 1) * BUFSTR;
            #pragma unroll
            for (int i = 0; i < 2; i++) {
                int idx = t + i * NTHR;
                int c = idx & 31, k = idx >> 5;
                uint32_t h0, l0, h1, l1;
                split2(kreg[i].x, kreg[i].y, h0, l0);
                split2(kreg[i].z, kreg[i].w, h1, l1);
                *(uint2*)(kv + KHOFF + k * RSTRB + c * 8) = make_uint2(h0, h1);
                *(uint2*)(kv + KLOFF + k * RSTRB + c * 8) = make_uint2(l0, l1);
                split2(vreg[i].x, vreg[i].y, h0, l0);
                split2(vreg[i].z, vreg[i].w, h1, l1);
                *(uint2*)(kv + VHOFF + k * RSTRB + c * 8) = make_uint2(h0, h1);
                *(uint2*)(kv + VLOFF + k * RSTRB + c * 8) = make_uint2(l0, l1);
            }
        }
        __syncthreads();
    }

    // ---- row sums: quad-reduce, then merge dh halves via shared atomics ----
    rs_lo += __shfl_xor_sync(0xffffffffu, rs_lo, 1);
    rs_lo += __shfl_xor_sync(0xffffffffu, rs_lo, 2);
    rs_hi += __shfl_xor_sync(0xffffffffu, rs_hi, 1);
    rs_hi += __shfl_xor_sync(0xffffffffu, rs_hi, 2);
    if (tg == 0) {
        atomicAdd(&RS[half * 64 + 16 * qb + g],     rs_lo);
        atomicAdd(&RS[half * 64 + 16 * qb + g + 8], rs_hi);
    }
    __syncthreads();

    // ---- O2 warps publish their C-frags (OB aliases Q region; loop done) ----
    if (half == 1) {
        #pragma unroll
        for (int nb = 0; nb < 8; nb++) {
            const int col = 64 * dh + 8 * nb + 2 * tg;
            *(float2*)(OB + (16 * qb + g)     * OBSTR + col) = make_float2(o[nb][0], o[nb][1]);
            *(float2*)(OB + (16 * qb + g + 8) * OBSTR + col) = make_float2(o[nb][2], o[nb][3]);
        }
    }
    __syncthreads();

    // ---- O1 warps combine + store ----
    if (half == 0) {
        const float il1_lo = 1.f / RS[16 * qb + g];
        const float il1_hi = 1.f / RS[16 * qb + g + 8];
        const float il2_lo = LAMBDA_V / RS[64 + 16 * qb + g];
        const float il2_hi = LAMBDA_V / RS[64 + 16 * qb + g + 8];
        float* orow_lo = Og + (size_t)(16 * qb + g) * DIM;
        float* orow_hi = Og + (size_t)(16 * qb + g + 8) * DIM;
        #pragma unroll
        for (int nb = 0; nb < 8; nb++) {
            const int col = 64 * dh + 8 * nb + 2 * tg;
            float2 o2a = *(float2*)(OB + (16 * qb + g)     * OBSTR + col);
            float2 o2b = *(float2*)(OB + (16 * qb + g + 8) * OBSTR + col);
            float2 ra, rb;
            ra.x = (o[nb][0] * il1_lo - o2a.x * il2_lo) * OUT_SCALE;
            ra.y = (o[nb][1] * il1_lo - o2a.y * il2_lo) * OUT_SCALE;
            rb.x = (o[nb][2] * il1_hi - o2b.x * il2_hi) * OUT_SCALE;
            rb.y = (o[nb][3] * il1_hi - o2b.y * il2_hi) * OUT_SCALE;
            *(float2*)(orow_lo + col) = ra;
            *(float2*)(orow_hi + col) = rb;
        }
    }
}

extern "C" void kernel_launch(void* const* d_in, const int* in_sizes, int n_in,
                              void* d_out, int out_size)
{
    const float* Q = (const float*)d_in[0];
    const float* K = (const float*)d_in[1];
    const float* V = (const float*)d_in[2];
    float* O = (float*)d_out;

    cudaFuncSetAttribute(diffattn_mma4_kernel,
                         cudaFuncAttributeMaxDynamicSharedMemorySize, SMEM_BYTES);

    diffattn_mma4_kernel<<<QTILES * NHEADS, NTHR, SMEM_BYTES>>>(Q, K, V, O);
}

// round 15
// speedup vs baseline: 1.3470x; 1.3470x over previous
#include <cuda_runtime.h>
#include <cuda_bf16.h>
#include <cstdint>

// Differential attention via warp-level bf16 MMA (mma.sync m16n8k16, sm_80+ ISA).
// Two launches: (1) pre-convert K/V fp32 -> bf16 hi/lo planes in smem-layout
// global scratch; (2) flash kernel whose K/V loads are pure cp.async (LDGSTS),
// double-buffered and overlapped with MMA. No per-tile convert work.
// Q (1,16,2048,128) fp32, K/V (1,4,2048,128) fp32, out fp32. Causal, GQA rep=4.
// Per half h: S_h = (Q_h K_h^T)/8; P_h = exp(S_h) (no max shift; |S| small),
// masked -> 0.  O_h = sum P_h V (fp32 accum in MMA C-frags).
// out = (O1/l1 - 0.8*O2/l2) * 0.2,  l = rowsum(P).
// Precision: x ~= xh + xl (bf16 each); X*Y ~= Xh*Yh + Xl*Yh + Xh*Yl.

#define S_LEN   2048
#define NHEADS  16
#define NKVH    4
#define DIM     128
#define HALF    64
#define BQ      64
#define BK      32
#define NTHR    256
#define QTILES  (S_LEN / BQ)      // 32

#define SCALE_QK   0.125f
#define LAMBDA_V   0.8f
#define OUT_SCALE  0.19999999999999996f

// padded row: 136 bf16 = 272 bytes (16B aligned, bank-spread)
#define RPAD   136
#define RSTRB  272
// pre-converted K/V planes: [plane][kvh][row][RPAD] bf16
// plane 0 = K hi, 1 = K lo, 2 = V hi, 3 = V lo
__device__ __align__(16) uint16_t g_kvconv[4][NKVH][S_LEN][RPAD];

// smem byte map (main kernel)
#define OFF_QH   0                  // 64 x 272 = 17408
#define OFF_QL   17408
#define OFF_B0   34816              // K/V buffer 0 (KH,KL,VH,VL x 8704)
#define BUFSTR   34816              // buffer stride (B1 = 69632)
#define KHOFF    0
#define KLOFF    8704
#define VHOFF    17408
#define VLOFF    26112
#define OFF_RS   104448             // RS1[64] f32 then RS2[64] f32
#define SMEM_BYTES 104960
// epilogue O2 exchange buffer reuses Q region: f32 [64][132]
#define OFF_OB   0
#define OBSTR    132

// chunks per tile: 4 planes x 32 rows x 17 x 16B = 2176
#define TILE_CHUNKS 2176

__device__ __forceinline__ uint32_t smem_u32(const void* p) {
    uint32_t a;
    asm("{ .reg .u64 t; cvta.to.shared.u64 t, %1; cvt.u32.u64 %0, t; }"
        : "=r"(a) : "l"(p));
    return a;
}
__device__ __forceinline__ void ldsm4(uint32_t* r, uint32_t a) {
    asm volatile("ldmatrix.sync.aligned.m8n8.x4.shared.b16 {%0,%1,%2,%3}, [%4];"
        : "=r"(r[0]), "=r"(r[1]), "=r"(r[2]), "=r"(r[3]) : "r"(a));
}
__device__ __forceinline__ void ldsm4t(uint32_t* r, uint32_t a) {
    asm volatile("ldmatrix.sync.aligned.m8n8.x4.trans.shared.b16 {%0,%1,%2,%3}, [%4];"
        : "=r"(r[0]), "=r"(r[1]), "=r"(r[2]), "=r"(r[3]) : "r"(a));
}
__device__ __forceinline__ void mma16816(float* c, const uint32_t* a,
                                         uint32_t b0, uint32_t b1) {
    asm volatile("mma.sync.aligned.m16n8k16.row.col.f32.bf16.bf16.f32 "
        "{%0,%1,%2,%3}, {%4,%5,%6,%7}, {%8,%9}, {%0,%1,%2,%3};"
        : "+f"(c[0]), "+f"(c[1]), "+f"(c[2]), "+f"(c[3])
        : "r"(a[0]), "r"(a[1]), "r"(a[2]), "r"(a[3]), "r"(b0), "r"(b1));
}
__device__ __forceinline__ void cp16(uint32_t dst_shared, const void* src) {
    asm volatile("cp.async.ca.shared.global [%0], [%1], 16;"
        :: "r"(dst_shared), "l"(src) : "memory");
}
#define CP_COMMIT() asm volatile("cp.async.commit_group;" ::: "memory")
#define CP_WAIT0()  asm volatile("cp.async.wait_group 0;" ::: "memory")

// split two floats into packed bf16x2 hi and lo (x = hi + lo)
__device__ __forceinline__ void split2(float x0, float x1, uint32_t& h, uint32_t& l) {
    __nv_bfloat16 h0 = __float2bfloat16(x0), h1 = __float2bfloat16(x1);
    __nv_bfloat16 l0 = __float2bfloat16(x0 - __bfloat162float(h0));
    __nv_bfloat16 l1 = __float2bfloat16(x1 - __bfloat162float(h1));
    h = (uint32_t)__bfloat16_as_ushort(h0) | ((uint32_t)__bfloat16_as_ushort(h1) << 16);
    l = (uint32_t)__bfloat16_as_ushort(l0) | ((uint32_t)__bfloat16_as_ushort(l1) << 16);
}

// ---------------- pre-pass: K/V fp32 -> bf16 hi/lo planes ----------------
__global__ __launch_bounds__(128)
void convert_kv_kernel(const float* __restrict__ Kg, const float* __restrict__ Vg)
{
    const int row = blockIdx.x;              // 0..8191 = kvh*2048 + r
    const int kvh = row >> 11, r = row & 2047;
    const int d = threadIdx.x;               // 0..127
    const size_t off = ((size_t)kvh * S_LEN + r) * DIM + d;

    float kv = Kg[off];
    __nv_bfloat16 hh = __float2bfloat16(kv);
    __nv_bfloat16 ll = __float2bfloat16(kv - __bfloat162float(hh));
    g_kvconv[0][kvh][r][d] = __bfloat16_as_ushort(hh);
    g_kvconv[1][kvh][r][d] = __bfloat16_as_ushort(ll);

    float vv = Vg[off];
    hh = __float2bfloat16(vv);
    ll = __float2bfloat16(vv - __bfloat162float(hh));
    g_kvconv[2][kvh][r][d] = __bfloat16_as_ushort(hh);
    g_kvconv[3][kvh][r][d] = __bfloat16_as_ushort(ll);
}

// ---------------- main flash kernel ----------------
__global__ __launch_bounds__(NTHR, 1)
void diffattn_mma5_kernel(const float* __restrict__ Qg_all,
                          float* __restrict__ Og_all)
{
    extern __shared__ char smc[];
    const uint32_t sb = smem_u32(smc);
    float* RS = (float*)(smc + OFF_RS);      // RS[0..63]=l1, RS[64..127]=l2
    float* OB = (float*)(smc + OFF_OB);      // epilogue only

    const int bid = blockIdx.x;
    const int h   = bid & 15;
    const int qt  = (QTILES - 1) - (bid >> 4);   // heavy q-tiles first
    const int kvh = h >> 2;
    const int t   = threadIdx.x;
    const int w   = t >> 5;
    const int lane = t & 31;
    const int g    = lane >> 2;     // 0..7
    const int tg   = lane & 3;      // 0..3
    const int l8   = lane & 7;
    const int mq   = lane >> 3;     // 0..3 (ldmatrix quad)
    const int half = w >> 2;        // 0: attn1, 1: attn2
    const int qb   = w & 3;         // 16-row stripe
    const int d0h  = half * HALF;

    const float* Qg = Qg_all + ((size_t)h * S_LEN + (size_t)qt * BQ) * DIM;
    float*       Og = Og_all + ((size_t)h * S_LEN + (size_t)qt * BQ) * DIM;

    // per-thread cp.async slot: idx = t + i*NTHR over [0, TILE_CHUNKS)
    // chunk c = idx % 17, row-plane rp = idx / 17 (p = rp>>5, k = rp&31)

    // ---- prologue: zero RS; issue tile-0 cp.async; Q convert/store ----
    if (t < 128) RS[t] = 0.f;
    {
        #pragma unroll
        for (int i = 0; i < 9; i++) {
            int idx = t + i * NTHR;
            if (idx < TILE_CHUNKS) {
                int c = idx % 17, rp = idx / 17;
                int p = rp >> 5, k = rp & 31;
                const char* src = (const char*)&g_kvconv[p][kvh][k][0] + c * 16;
                cp16(sb + OFF_B0 + p * 8704 + k * RSTRB + c * 16, src);
            }
        }
        CP_COMMIT();
    }
    {
        const float4* Qg4 = (const float4*)Qg;
        #pragma unroll
        for (int i = 0; i < 8; i++) {
            int idx = t + i * NTHR;          // 0..2047
            int c = idx & 31, q = idx >> 5;
            float4 v = Qg4[idx];
            v.x *= SCALE_QK; v.y *= SCALE_QK; v.z *= SCALE_QK; v.w *= SCALE_QK;
            uint32_t h0, l0, h1, l1;
            split2(v.x, v.y, h0, l0);
            split2(v.z, v.w, h1, l1);
            *(uint2*)(smc + OFF_QH + q * RSTRB + c * 8) = make_uint2(h0, h1);
            *(uint2*)(smc + OFF_QL + q * RSTRB + c * 8) = make_uint2(l0, l1);
        }
    }
    CP_WAIT0();
    __syncthreads();

    uint32_t qhf[4][4], qlf[4][4];   // Q A-frags per k-step (persistent)
    {
        const int row = 16 * qb + (mq & 1) * 8 + l8;
        #pragma unroll
        for (int s = 0; s < 4; s++) {
            const int col = d0h + 16 * s + (mq >> 1) * 8;
            ldsm4(qhf[s], sb + OFF_QH + row * RSTRB + col * 2);
            ldsm4(qlf[s], sb + OFF_QL + row * RSTRB + col * 2);
        }
    }

    // ---- persistent state ----
    float o[16][4];                  // O C-frags, dims 8*nb + {2tg,2tg+1}
    #pragma unroll
    for (int nb = 0; nb < 16; nb++)
        #pragma unroll
        for (int e = 0; e < 4; e++) o[nb][e] = 0.f;
    float rs_lo = 0.f, rs_hi = 0.f;  // partial row sums (rows 16qb+g, +8)

    const int qbase = qt * BQ;
    const int q_lo = qbase + 16 * qb + g;
    const int q_hi = q_lo + 8;
    const int nkt = 2 * qt + 2;

    for (int kt = 0; kt < nkt; kt++) {
        const int kbase = kt * BK;
        const uint32_t kvb = sb + OFF_B0 + (uint32_t)(kt & 1) * BUFSTR;
        const bool pf = (kt + 1 < nkt);

        // ---- issue cp.async for next tile into the other buffer ----
        if (pf) {
            const uint32_t dstb = sb + OFF_B0 + (uint32_t)((kt + 1) & 1) * BUFSTR;
            const int nb = kbase + BK;
            #pragma unroll
            for (int i = 0; i < 9; i++) {
                int idx = t + i * NTHR;
                if (idx < TILE_CHUNKS) {
                    int c = idx % 17, rp = idx / 17;
                    int p = rp >> 5, k = rp & 31;
                    const char* src = (const char*)&g_kvconv[p][kvh][nb + k][0] + c * 16;
                    cp16(dstb + p * 8704 + k * RSTRB + c * 16, src);
                }
            }
            CP_COMMIT();
        }

        // ---- QK: S C-frags (4 key-blocks x 4 elems), 3-term bf16 split ----
        float c4[4][4];
        #pragma unroll
        for (int kb = 0; kb < 4; kb++)
            #pragma unroll
            for (int e = 0; e < 4; e++) c4[kb][e] = 0.f;

        #pragma unroll
        for (int s = 0; s < 4; s++) {
            const int col = d0h + 16 * s + (mq & 1) * 8;
            uint32_t kh01[4], kh23[4], kl01[4], kl23[4];
            {
                const int r01 = 8 * (0 + (mq >> 1)) + l8;   // keys kb 0/1
                const int r23 = 8 * (2 + (mq >> 1)) + l8;   // keys kb 2/3
                ldsm4(kh01, kvb + KHOFF + r01 * RSTRB + col * 2);
                ldsm4(kh23, kvb + KHOFF + r23 * RSTRB + col * 2);
                ldsm4(kl01, kvb + KLOFF + r01 * RSTRB + col * 2);
                ldsm4(kl23, kvb + KLOFF + r23 * RSTRB + col * 2);
            }
            mma16816(c4[0], qhf[s], kh01[0], kh01[1]);
            mma16816(c4[1], qhf[s], kh01[2], kh01[3]);
            mma16816(c4[2], qhf[s], kh23[0], kh23[1]);
            mma16816(c4[3], qhf[s], kh23[2], kh23[3]);
            mma16816(c4[0], qlf[s], kh01[0], kh01[1]);
            mma16816(c4[1], qlf[s], kh01[2], kh01[3]);
            mma16816(c4[2], qlf[s], kh23[0], kh23[1]);
            mma16816(c4[3], qlf[s], kh23[2], kh23[3]);
            mma16816(c4[0], qhf[s], kl01[0], kl01[1]);
            mma16816(c4[1], qhf[s], kl01[2], kl01[3]);
            mma16816(c4[2], qhf[s], kl23[0], kl23[1]);
            mma16816(c4[3], qhf[s], kl23[2], kl23[3]);
        }

        // ---- exp + mask in registers; pack P as A-frags (hi/lo) ----
        uint32_t pah[2][4], pal[2][4];
        #pragma unroll
        for (int kb = 0; kb < 4; kb++) {
            const int k0 = kbase + 8 * kb + 2 * tg;
            float p00 = (k0     <= q_lo) ? __expf(c4[kb][0]) : 0.f;
            float p01 = (k0 + 1 <= q_lo) ? __expf(c4[kb][1]) : 0.f;
            float p10 = (k0     <= q_hi) ? __expf(c4[kb][2]) : 0.f;
            float p11 = (k0 + 1 <= q_hi) ? __expf(c4[kb][3]) : 0.f;
            rs_lo += p00 + p01;
            rs_hi += p10 + p11;
            const int ks = kb >> 1, part = kb & 1;
            split2(p00, p01, pah[ks][2 * part + 0], pal[ks][2 * part + 0]);
            split2(p10, p11, pah[ks][2 * part + 1], pal[ks][2 * part + 1]);
        }

        // ---- PV: O += Ph*Vh + Pl*Vh + Ph*Vl ----
        #pragma unroll
        for (int ks = 0; ks < 2; ks++) {
            const int vrow = 16 * ks + (mq & 1) * 8 + l8;
            #pragma unroll
            for (int nbp = 0; nbp < 8; nbp++) {
                const int vcol = 8 * (2 * nbp + (mq >> 1));
                uint32_t vh[4], vl[4];
                ldsm4t(vh, kvb + VHOFF + vrow * RSTRB + vcol * 2);
                ldsm4t(vl, kvb + VLOFF + vrow * RSTRB + vcol * 2);
                const int nb0 = 2 * nbp, nb1 = nb0 + 1;
                mma16816(o[nb0], pah[ks], vh[0], vh[1]);
                mma16816(o[nb1], pah[ks], vh[2], vh[3]);
                mma16816(o[nb0], pal[ks], vh[0], vh[1]);
                mma16816(o[nb1], pal[ks], vh[2], vh[3]);
                mma16816(o[nb0], pah[ks], vl[0], vl[1]);
                mma16816(o[nb1], pah[ks], vl[2], vl[3]);
            }
        }

        // ---- wait for next tile's copy (overlapped with the MMAs above) ----
        if (pf) CP_WAIT0();
        __syncthreads();
    }

    // ---- row sums: reduce over tg quad, publish ----
    rs_lo += __shfl_xor_sync(0xffffffffu, rs_lo, 1);
    rs_lo += __shfl_xor_sync(0xffffffffu, rs_lo, 2);
    rs_hi += __shfl_xor_sync(0xffffffffu, rs_hi, 1);
    rs_hi += __shfl_xor_sync(0xffffffffu, rs_hi, 2);
    if (tg == 0) {
        RS[half * 64 + 16 * qb + g]     = rs_lo;
        RS[half * 64 + 16 * qb + g + 8] = rs_hi;
    }
    // ---- O2 warps publish their C-frags (OB aliases Q region; loop done) ----
    if (half == 1) {
        #pragma unroll
        for (int nb = 0; nb < 16; nb++) {
            const int col = 8 * nb + 2 * tg;
            *(float2*)(OB + (16 * qb + g)     * OBSTR + col) = make_float2(o[nb][0], o[nb][1]);
            *(float2*)(OB + (16 * qb + g + 8) * OBSTR + col) = make_float2(o[nb][2], o[nb][3]);
        }
    }
    __syncthreads();

    // ---- O1 warps combine + store ----
    if (half == 0) {
        const float il1_lo = 1.f / RS[16 * qb + g];
        const float il1_hi = 1.f / RS[16 * qb + g + 8];
        const float il2_lo = LAMBDA_V / RS[64 + 16 * qb + g];
        const float il2_hi = LAMBDA_V / RS[64 + 16 * qb + g + 8];
        float* orow_lo = Og + (size_t)(16 * qb + g) * DIM;
        float* orow_hi = Og + (size_t)(16 * qb + g + 8) * DIM;
        #pragma unroll
        for (int nb = 0; nb < 16; nb++) {
            const int col = 8 * nb + 2 * tg;
            float2 o2a = *(float2*)(OB + (16 * qb + g)     * OBSTR + col);
            float2 o2b = *(float2*)(OB + (16 * qb + g + 8) * OBSTR + col);
            float2 ra, rb;
            ra.x = (o[nb][0] * il1_lo - o2a.x * il2_lo) * OUT_SCALE;
            ra.y = (o[nb][1] * il1_lo - o2a.y * il2_lo) * OUT_SCALE;
            rb.x = (o[nb][2] * il1_hi - o2b.x * il2_hi) * OUT_SCALE;
            rb.y = (o[nb][3] * il1_hi - o2b.y * il2_hi) * OUT_SCALE;
            *(float2*)(orow_lo + col) = ra;
            *(float2*)(orow_hi + col) = rb;
        }
    }
}

extern "C" void kernel_launch(void* const* d_in, const int* in_sizes, int n_in,
                              void* d_out, int out_size)
{
    const float* Q = (const float*)d_in[0];
    const float* K = (const float*)d_in[1];
    const float* V = (const float*)d_in[2];
    float* O = (float*)d_out;

    cudaFuncSetAttribute(diffattn_mma5_kernel,
                         cudaFuncAttributeMaxDynamicSharedMemorySize, SMEM_BYTES);

    convert_kv_kernel<<<NKVH * S_LEN, 128>>>(K, V);
    diffattn_mma5_kernel<<<QTILES * NHEADS, NTHR, SMEM_BYTES>>>(Q, O);
}